// round 11
// baseline (speedup 1.0000x reference)
#include <cuda_runtime.h>
#include <cstdint>

// Inputs (metadata order):
//   0 origins [N,3] f32   1 directions [N,3] f32   2 center [3] f32
//   3 radius  [1]  f32    4 W1 [3,128] f32         5 b1 [128] f32
//   6 W2 [128,3] f32      7 b2 [3] f32
// Output: color [N,3] f32

#define MAX_ITERS 64
#define NUNIT 128         // hidden units
#define TPB 128
#define RPT 4             // rays per thread = 2 ray-pairs packed in f32x2

typedef unsigned long long ull;

// Union-based pack/unpack: lets ptxas alias register pairs instead of
// forcing MOVs (the old mov.b64 asm pinned real moves).
static __device__ __forceinline__ ull pack2(float lo, float hi) {
    union { float2 f; ull u; } t;
    t.f = make_float2(lo, hi);
    return t.u;
}
static __device__ __forceinline__ void unpack2(ull v, float& lo, float& hi) {
    union { float2 f; ull u; } t;
    t.u = v;
    lo = t.f.x;
    hi = t.f.y;
}
// Packed dual-fp32 FMA (Blackwell f32x2 pipe; ptxas never emits this from C++)
static __device__ __forceinline__ ull ffma2(ull a, ull b, ull c) {
    ull d;
    asm("fma.rn.f32x2 %0, %1, %2, %3;" : "=l"(d) : "l"(a), "l"(b), "l"(c));
    return d;
}
// Single-MUFU sqrt (rel err ~3.4e-7)
static __device__ __forceinline__ float fsqrt_fast(float x) {
    float y;
    asm("sqrt.approx.f32 %0, %1;" : "=f"(y) : "f"(x));
    return y;
}

// Per-hidden-unit weights, every scalar pre-duplicated into both f32x2 halves
// (the ray-pair occupies the halves; the weight must be uniform across them).
// 64B stride: 16B-aligned for LDS.128, broadcast access -> conflict-free.
struct alignas(16) SUnit {
    ulonglong2 A;   // { {W1[0][j],W1[0][j]}, {W1[1][j],W1[1][j]} }
    ulonglong2 B;   // { {W1[2][j],W1[2][j]}, {b1[j],   b1[j]}    }
    ulonglong2 C;   // { {W2[j][0],W2[j][0]}, {W2[j][1],W2[j][1]} }
    ull        D;   // { W2[j][2], W2[j][2] }
    ull        pad;
};

__global__ __launch_bounds__(TPB, 10)
void sphere_trace_mlp_kernel(
    const float* __restrict__ origins,
    const float* __restrict__ dirs,
    const float* __restrict__ center,
    const float* __restrict__ radius,
    const float* __restrict__ W1,   // [3,128] row-major
    const float* __restrict__ b1,   // [128]
    const float* __restrict__ W2,   // [128,3] row-major
    const float* __restrict__ b2,   // [3]
    float* __restrict__ out,        // [N,3]
    int n)
{
    __shared__ SUnit sW[NUNIT];     // 8 KB

    const int tid = threadIdx.x;
    {   // TPB == NUNIT: one unit per thread
        const int j = tid;
        SUnit w;
        w.A.x = pack2(W1[j],       W1[j]);
        w.A.y = pack2(W1[128 + j], W1[128 + j]);
        w.B.x = pack2(W1[256 + j], W1[256 + j]);
        w.B.y = pack2(b1[j],       b1[j]);
        w.C.x = pack2(W2[3 * j],     W2[3 * j]);
        w.C.y = pack2(W2[3 * j + 1], W2[3 * j + 1]);
        w.D   = pack2(W2[3 * j + 2], W2[3 * j + 2]);
        w.pad = 0ull;
        sW[j] = w;
    }

    const int base = blockIdx.x * (TPB * RPT) + tid;

    const float cx = center[0], cy = center[1], cz = center[2];
    const float r  = radius[0];
    const float r2 = r * r;

    // ---- Ray classification (replaces the 64-iter march) ----
    // Unit d => sdf(t) = sqrt(t^2 + 2*hb*t + c0) - r, hb = (o-c).d, c0 = |o-c|^2.
    // Sphere tracing converges to t* = -hb - sqrt(disc), disc = hb^2 - c0 + r^2,
    // per-step contraction q = 1 - cos(alpha), cos(alpha) = sqrt(disc)/r.
    //  clear hit  (hb<0, disc > 0.04 r^2): ref s64 <= 0.8^63 ~ 8e-7 << eps and
    //     |t* - t64| <= 4e-6 -> identical mask & color.
    //  clear miss (hb>=0, or disc <= -2e-4): ref s64 > 1e-4 -> zeroed anyway.
    //  band (else, P ~ 4e-6/ray): exact 64-iteration reference recurrence.
    float tt[RPT], hbv[RPT], c0v[RPT];
    bool  hit[RPT];
    bool  band_any = false;

    #pragma unroll
    for (int k = 0; k < RPT; ++k) {
        const int g = base + k * TPB;         // coalesced per-k
        const int i = (g < n) ? g : (n - 1);  // inert clamp for tail
        const float ux = origins[3 * i]     - cx;
        const float uy = origins[3 * i + 1] - cy;
        const float uz = origins[3 * i + 2] - cz;
        const float dx = dirs[3 * i], dy = dirs[3 * i + 1], dz = dirs[3 * i + 2];
        const float c0 = fmaf(ux, ux, fmaf(uy, uy, uz * uz));
        const float hb = fmaf(ux, dx, fmaf(uy, dy, uz * dz));
        const float disc = fmaf(hb, hb, r2 - c0);
        const bool  toward = (hb < 0.0f);
        const bool  clear_hit = toward && (disc > 0.04f * r2);
        const bool  in_band = toward && !clear_hit && (disc > -2e-4f);
        band_any |= in_band;
        hit[k] = clear_hit;
        tt[k]  = clear_hit ? (-hb - fsqrt_fast(disc)) : 0.0f;
        hbv[k] = hb;
        c0v[k] = c0;
    }

    if (__any_sync(0xffffffffu, band_any)) {
        // Rare path (~5e-4 of warps): exact reference loop, all rays recomputed.
        #pragma unroll
        for (int k = 0; k < RPT; ++k) {
            const float b = 2.0f * hbv[k];
            float t = 0.0f, s = 0.0f;
            #pragma unroll 1
            for (int it = 0; it < MAX_ITERS; ++it) {
                s = sqrtf(fmaf(t, t + b, c0v[k])) - r;
                t += s;
            }
            hit[k] = (s < 1e-4f);
            tt[k]  = t;
        }
    }

    __syncthreads();   // shared weights ready

    // ---- MLP with ray-pair f32x2 packing ----
    // Pair q holds rays (2q, 2q+1) in the low/high halves. Per hidden unit j:
    // h = {h_j(r0), h_j(r1)} via 3 FFMA2; packed relu; 3 FFMA2 accumulate into
    // a0/a1/a2 = per-ray output channels. Live packed state: 6 pairs = 12 regs
    // (was 24), no cross-half reduction needed in the epilogue.
    ull px2[2], py2[2], pz2[2];
    ull a0[2], a1[2], a2[2];
    #pragma unroll
    for (int q = 0; q < 2; ++q) {
        float p3[2][3];
        #pragma unroll
        for (int jj = 0; jj < 2; ++jj) {
            const int k = 2 * q + jj;
            const int g = base + k * TPB;
            const int i = (g < n) ? g : (n - 1);
            p3[jj][0] = fmaf(tt[k], dirs[3 * i],     origins[3 * i]);
            p3[jj][1] = fmaf(tt[k], dirs[3 * i + 1], origins[3 * i + 1]);
            p3[jj][2] = fmaf(tt[k], dirs[3 * i + 2], origins[3 * i + 2]);
        }
        px2[q] = pack2(p3[0][0], p3[1][0]);
        py2[q] = pack2(p3[0][1], p3[1][1]);
        pz2[q] = pack2(p3[0][2], p3[1][2]);
        a0[q] = 0ull; a1[q] = 0ull; a2[q] = 0ull;
    }

    #pragma unroll 8
    for (int j = 0; j < NUNIT; ++j) {
        const ulonglong2 A = sW[j].A;
        const ulonglong2 B = sW[j].B;
        const ulonglong2 C = sW[j].C;
        const ull        D = sW[j].D;
        #pragma unroll
        for (int q = 0; q < 2; ++q) {
            ull h = B.y;
            h = ffma2(px2[q], A.x, h);
            h = ffma2(py2[q], A.y, h);
            h = ffma2(pz2[q], B.x, h);
            float hl, hh;
            unpack2(h, hl, hh);
            hl = fmaxf(hl, 0.0f);          // relu halves (alu pipe)
            hh = fmaxf(hh, 0.0f);
            h = pack2(hl, hh);
            a0[q] = ffma2(h, C.x, a0[q]);
            a1[q] = ffma2(h, C.y, a1[q]);
            a2[q] = ffma2(h, D,   a2[q]);
        }
    }

    const float bb0 = b2[0], bb1 = b2[1], bb2 = b2[2];
    #pragma unroll
    for (int q = 0; q < 2; ++q) {
        float z0[2], z1[2], z2[2];
        unpack2(a0[q], z0[0], z0[1]);
        unpack2(a1[q], z1[0], z1[1]);
        unpack2(a2[q], z2[0], z2[1]);
        #pragma unroll
        for (int jj = 0; jj < 2; ++jj) {
            const int k = 2 * q + jj;
            const int g = base + k * TPB;
            const float c0 = __fdividef(1.0f, 1.0f + __expf(-(bb0 + z0[jj])));
            const float c1 = __fdividef(1.0f, 1.0f + __expf(-(bb1 + z1[jj])));
            const float c2 = __fdividef(1.0f, 1.0f + __expf(-(bb2 + z2[jj])));
            if (g < n) {
                out[3 * g]     = hit[k] ? c0 : 0.0f;
                out[3 * g + 1] = hit[k] ? c1 : 0.0f;
                out[3 * g + 2] = hit[k] ? c2 : 0.0f;
            }
        }
    }
}

extern "C" void kernel_launch(void* const* d_in, const int* in_sizes, int n_in,
                              void* d_out, int out_size) {
    const float* origins = (const float*)d_in[0];
    const float* dirs    = (const float*)d_in[1];
    const float* center  = (const float*)d_in[2];
    const float* radius  = (const float*)d_in[3];
    const float* W1      = (const float*)d_in[4];
    const float* b1      = (const float*)d_in[5];
    const float* W2      = (const float*)d_in[6];
    const float* b2      = (const float*)d_in[7];
    float* out = (float*)d_out;

    const int n = in_sizes[0] / 3;
    const int per_block = TPB * RPT;
    const int blocks = (n + per_block - 1) / per_block;
    sphere_trace_mlp_kernel<<<blocks, TPB>>>(origins, dirs, center, radius,
                                             W1, b1, W2, b2, out, n);
}

// round 13
// speedup vs baseline: 1.7604x; 1.7604x over previous
#include <cuda_runtime.h>
#include <cstdint>

// Inputs (metadata order):
//   0 origins [N,3] f32   1 directions [N,3] f32   2 center [3] f32
//   3 radius  [1]  f32    4 W1 [3,128] f32         5 b1 [128] f32
//   6 W2 [128,3] f32      7 b2 [3] f32
// Output: color [N,3] f32

#define MAX_ITERS 64
#define NPAIR 64          // 128 hidden units as 64 f32x2 pairs
#define TPB 128
#define RPT 4             // rays per thread

typedef unsigned long long ull;

// Union-based pack/unpack: ptxas aliases the f32x2 halves onto the register
// pair in place (R11 evidence: regs 64->48, no MOV storm). The old asm
// mov.b64 version pinned ~1024 real MOVs per thread around the relus.
static __device__ __forceinline__ ull pack2(float lo, float hi) {
    union { float2 f; ull u; } t;
    t.f = make_float2(lo, hi);
    return t.u;
}
static __device__ __forceinline__ void unpack2(ull v, float& lo, float& hi) {
    union { float2 f; ull u; } t;
    t.u = v;
    lo = t.f.x;
    hi = t.f.y;
}
// Packed dual-fp32 FMA (Blackwell f32x2 pipe; ptxas never emits this from C++)
static __device__ __forceinline__ ull ffma2(ull a, ull b, ull c) {
    ull d;
    asm("fma.rn.f32x2 %0, %1, %2, %3;" : "=l"(d) : "l"(a), "l"(b), "l"(c));
    return d;
}
// Single-MUFU sqrt (rel err ~3.4e-7)
static __device__ __forceinline__ float fsqrt_fast(float x) {
    float y;
    asm("sqrt.approx.f32 %0, %1;" : "=f"(y) : "f"(x));
    return y;
}

__global__ __launch_bounds__(TPB, 8)
void sphere_trace_mlp_kernel(
    const float* __restrict__ origins,
    const float* __restrict__ dirs,
    const float* __restrict__ center,
    const float* __restrict__ radius,
    const float* __restrict__ W1,   // [3,128] row-major
    const float* __restrict__ b1,   // [128]
    const float* __restrict__ W2,   // [128,3] row-major
    const float* __restrict__ b2,   // [3]
    float* __restrict__ out,        // [N,3]
    int n)
{
    // Shared weights, pre-packed for f32x2 consumption. Pair p = units (2p, 2p+1).
    __shared__ float4 sA[NPAIR];  // {W1[0][j], W1[0][j+1], W1[1][j], W1[1][j+1]}
    __shared__ float4 sB[NPAIR];  // {W1[2][j], W1[2][j+1], b1[j],    b1[j+1]}
    __shared__ float4 sC[NPAIR];  // {W2[j][0], W2[j+1][0], W2[j][1], W2[j+1][1]}
    __shared__ float2 sD[NPAIR];  // {W2[j][2], W2[j+1][2]}

    const int tid = threadIdx.x;
    if (tid < NPAIR) {
        const int j = 2 * tid;
        sA[tid] = make_float4(W1[j],       W1[j + 1],
                              W1[128 + j], W1[128 + j + 1]);
        sB[tid] = make_float4(W1[256 + j], W1[256 + j + 1],
                              b1[j],       b1[j + 1]);
        sC[tid] = make_float4(W2[3 * j],     W2[3 * j + 3],
                              W2[3 * j + 1], W2[3 * j + 4]);
        sD[tid] = make_float2(W2[3 * j + 2], W2[3 * j + 5]);
    }

    const int base = blockIdx.x * (TPB * RPT) + tid;

    const float cx = center[0], cy = center[1], cz = center[2];
    const float r  = radius[0];
    const float r2 = r * r;

    // ---- Ray classification (replaces the 64-iter march) ----
    // Unit d => sdf(t) = sqrt(t^2 + 2*hb*t + c0) - r, hb = (o-c).d, c0 = |o-c|^2.
    // Sphere tracing converges to t* = -hb - sqrt(disc), disc = hb^2 - c0 + r^2,
    // per-step contraction q = 1 - cos(alpha), cos(alpha) = sqrt(disc)/r.
    //  clear hit  (hb<0, disc > 0.04 r^2): ref s64 <= 0.8^63 ~ 8e-7 << eps and
    //     |t* - t64| <= 4e-6 -> identical mask & color.
    //  clear miss (hb>=0, or disc <= -2e-4): ref s64 > 1e-4 -> zeroed anyway.
    //  band (else, P ~ 4e-6/ray): exact 64-iteration reference recurrence.
    float tt[RPT], hbv[RPT], c0v[RPT];
    bool  hit[RPT];
    bool  band_any = false;

    #pragma unroll
    for (int k = 0; k < RPT; ++k) {
        const int g = base + k * TPB;         // coalesced per-k
        const int i = (g < n) ? g : (n - 1);  // inert clamp for tail
        const float ux = origins[3 * i]     - cx;
        const float uy = origins[3 * i + 1] - cy;
        const float uz = origins[3 * i + 2] - cz;
        const float dx = dirs[3 * i], dy = dirs[3 * i + 1], dz = dirs[3 * i + 2];
        const float c0 = fmaf(ux, ux, fmaf(uy, uy, uz * uz));
        const float hb = fmaf(ux, dx, fmaf(uy, dy, uz * dz));
        const float disc = fmaf(hb, hb, r2 - c0);
        const bool  toward = (hb < 0.0f);
        const bool  clear_hit = toward && (disc > 0.04f * r2);
        const bool  in_band = toward && !clear_hit && (disc > -2e-4f);
        band_any |= in_band;
        hit[k] = clear_hit;
        tt[k]  = clear_hit ? (-hb - fsqrt_fast(disc)) : 0.0f;
        hbv[k] = hb;
        c0v[k] = c0;
    }

    if (__any_sync(0xffffffffu, band_any)) {
        // Rare path (~5e-4 of warps): exact reference loop, all rays recomputed.
        #pragma unroll
        for (int k = 0; k < RPT; ++k) {
            const float b = 2.0f * hbv[k];
            float t = 0.0f, s = 0.0f;
            #pragma unroll 1
            for (int it = 0; it < MAX_ITERS; ++it) {
                s = sqrtf(fmaf(t, t + b, c0v[k])) - r;
                t += s;
            }
            hit[k] = (s < 1e-4f);
            tt[k]  = t;
        }
    }

    __syncthreads();   // shared weights ready

    // ---- MLP: h = relu(p@W1 + b1); col = sigmoid(h@W2 + b2), p = o + t*d.
    // Per pair: 4 broadcast LDS feed 24 FFMA2 (fma pipe) + 8 FMNMX (alu pipe),
    // with zero pack/unpack MOVs (in-place register-pair aliasing).
    ull px2[RPT], py2[RPT], pz2[RPT];
    ull a0[RPT], a1[RPT], a2[RPT];
    #pragma unroll
    for (int k = 0; k < RPT; ++k) {
        const int g = base + k * TPB;
        const int i = (g < n) ? g : (n - 1);
        const float px = fmaf(tt[k], dirs[3 * i],     origins[3 * i]);
        const float py = fmaf(tt[k], dirs[3 * i + 1], origins[3 * i + 1]);
        const float pz = fmaf(tt[k], dirs[3 * i + 2], origins[3 * i + 2]);
        px2[k] = pack2(px, px);
        py2[k] = pack2(py, py);
        pz2[k] = pack2(pz, pz);
        a0[k] = 0ull; a1[k] = 0ull; a2[k] = 0ull;
    }

    const ulonglong2* __restrict__ Au = (const ulonglong2*)sA;
    const ulonglong2* __restrict__ Bu = (const ulonglong2*)sB;
    const ulonglong2* __restrict__ Cu = (const ulonglong2*)sC;
    const ull*        __restrict__ Du = (const ull*)sD;

    // Double-buffered weight loads: pair p+1's LDS issue before pair p's math,
    // hiding the 29-cyc LDS latency under 24 FFMA2.
    ulonglong2 wa = Au[0], wb = Bu[0], wc = Cu[0];
    ull        wd = Du[0];

    #pragma unroll 8
    for (int p = 0; p < NPAIR; ++p) {
        const int q = (p + 1) & (NPAIR - 1);
        const ulonglong2 na = Au[q];
        const ulonglong2 nb = Bu[q];
        const ulonglong2 nc = Cu[q];
        const ull        nd = Du[q];

        #pragma unroll
        for (int k = 0; k < RPT; ++k) {
            ull h = wb.y;
            h = ffma2(px2[k], wa.x, h);
            h = ffma2(py2[k], wa.y, h);
            h = ffma2(pz2[k], wb.x, h);
            float hl, hh;
            unpack2(h, hl, hh);
            hl = fmaxf(hl, 0.0f);      // relu on the alu pipe (in-place)
            hh = fmaxf(hh, 0.0f);
            h = pack2(hl, hh);
            a0[k] = ffma2(h, wc.x, a0[k]);
            a1[k] = ffma2(h, wc.y, a1[k]);
            a2[k] = ffma2(h, wd,   a2[k]);
        }

        wa = na; wb = nb; wc = nc; wd = nd;
    }

    const float bb0 = b2[0], bb1 = b2[1], bb2 = b2[2];
    #pragma unroll
    for (int k = 0; k < RPT; ++k) {
        float l0, h0, l1, h1, l2, h2;
        unpack2(a0[k], l0, h0);
        unpack2(a1[k], l1, h1);
        unpack2(a2[k], l2, h2);
        const float z0 = bb0 + l0 + h0;
        const float z1 = bb1 + l1 + h1;
        const float z2 = bb2 + l2 + h2;
        const float c0 = __fdividef(1.0f, 1.0f + __expf(-z0));
        const float c1 = __fdividef(1.0f, 1.0f + __expf(-z1));
        const float c2 = __fdividef(1.0f, 1.0f + __expf(-z2));
        const int g = base + k * TPB;
        if (g < n) {
            out[3 * g]     = hit[k] ? c0 : 0.0f;
            out[3 * g + 1] = hit[k] ? c1 : 0.0f;
            out[3 * g + 2] = hit[k] ? c2 : 0.0f;
        }
    }
}

extern "C" void kernel_launch(void* const* d_in, const int* in_sizes, int n_in,
                              void* d_out, int out_size) {
    const float* origins = (const float*)d_in[0];
    const float* dirs    = (const float*)d_in[1];
    const float* center  = (const float*)d_in[2];
    const float* radius  = (const float*)d_in[3];
    const float* W1      = (const float*)d_in[4];
    const float* b1      = (const float*)d_in[5];
    const float* W2      = (const float*)d_in[6];
    const float* b2      = (const float*)d_in[7];
    float* out = (float*)d_out;

    const int n = in_sizes[0] / 3;
    const int per_block = TPB * RPT;
    const int blocks = (n + per_block - 1) / per_block;
    sphere_trace_mlp_kernel<<<blocks, TPB>>>(origins, dirs, center, radius,
                                             W1, b1, W2, b2, out, n);
}